// round 1
// baseline (speedup 1.0000x reference)
#include <cuda_runtime.h>

// KVCacheHeadAttention: B=32, E=4096, NH=32 -> D=128, MAX_TOKENS=2048.
// Reference broadcasting makes this a PREFIX-softmax:
//   out[b,s,:] = sum_{t<=s} e_t * v[b,t,:] / sum_{t<=s} e_t,
//   e_t = exp(q[b].k[b,t] / sqrt(D))   (global-max subtraction unnecessary:
//   scores ~ N(0,0.03..1.6), exp is safe in f32 and ratio is identical).
// k/v at t == next_pos[b] come from the fresh projections (inputs untouched).

#define BB 32
#define DD 128
#define EE 4096
#define MAXT 2048
#define CHUNK 128
#define MAXCH 16

__device__ float g_qkv[3][BB][DD];        // q,k,v projections
__device__ float g_e[BB][MAXT];           // exp(scores)
__device__ float g_cnum[BB][MAXCH][DD];   // per-chunk numerator totals
__device__ float g_cden[BB][MAXCH];       // per-chunk denominator totals

// ---------------------------------------------------------------- K0: zero
__global__ void zero_qkv_kernel() {
    int i = blockIdx.x * 256 + threadIdx.x;
    if (i < 3 * BB * DD) ((float*)g_qkv)[i] = 0.0f;
}

// ------------------------------------------------- K1: QKV split-K GEMM
// C[m][b][d] = sum_e x[b,e] * W_m[d,e].  Tile: 32 b x 32 d, e-chunk 128.
// grid(12 = 3 matrices * 4 d-tiles, 32 e-splits), 256 threads, 2x2/thread.
#define ECH 128
__global__ __launch_bounds__(256) void qkv_kernel(
    const float* __restrict__ x, const float* __restrict__ Wq,
    const float* __restrict__ Wk, const float* __restrict__ Wv) {
    __shared__ float xs[32][ECH + 4];
    __shared__ float ws[32][ECH + 4];
    int m  = blockIdx.x >> 2;
    int dt = blockIdx.x & 3;
    const float* W = (m == 0) ? Wq : ((m == 1) ? Wk : Wv);
    int e0  = blockIdx.y * ECH;
    int tid = threadIdx.x;

    // cooperative loads: 32 rows x 128 floats each = 1024 float4 / 256 thr
    for (int i = tid; i < 32 * (ECH / 4); i += 256) {
        int r = i >> 5;            // row
        int j = (i & 31) << 2;     // float offset
        *(float4*)&xs[r][j] = *(const float4*)(x + (size_t)r * EE + e0 + j);
        *(float4*)&ws[r][j] = *(const float4*)(W + (size_t)(dt * 32 + r) * EE + e0 + j);
    }
    __syncthreads();

    int ti = tid & 15, tj = tid >> 4;  // b-pair {ti,ti+16}, d-pair {tj,tj+16}
    float a00 = 0.f, a01 = 0.f, a10 = 0.f, a11 = 0.f;
    #pragma unroll
    for (int e = 0; e < ECH; e += 4) {
        float4 xa = *(float4*)&xs[ti][e];
        float4 xb = *(float4*)&xs[ti + 16][e];
        float4 wa = *(float4*)&ws[tj][e];
        float4 wb = *(float4*)&ws[tj + 16][e];
        a00 += xa.x*wa.x + xa.y*wa.y + xa.z*wa.z + xa.w*wa.w;
        a01 += xa.x*wb.x + xa.y*wb.y + xa.z*wb.z + xa.w*wb.w;
        a10 += xb.x*wa.x + xb.y*wa.y + xb.z*wa.z + xb.w*wa.w;
        a11 += xb.x*wb.x + xb.y*wb.y + xb.z*wb.z + xb.w*wb.w;
    }
    atomicAdd(&g_qkv[m][ti][dt * 32 + tj],           a00);
    atomicAdd(&g_qkv[m][ti][dt * 32 + tj + 16],      a01);
    atomicAdd(&g_qkv[m][ti + 16][dt * 32 + tj],      a10);
    atomicAdd(&g_qkv[m][ti + 16][dt * 32 + tj + 16], a11);
}

// ------------------- K2: scores -> exp, plus per-chunk num/den totals
// grid(nchunks, B), 128 threads. Phase 1: thread-per-token score dot (K read).
// Phase 2: thread-per-dim chunk numerator (V read).
__global__ __launch_bounds__(128) void score_chunk_kernel(
    const float* __restrict__ kv, const int* __restrict__ np, int max_k) {
    int b = blockIdx.y, c = blockIdx.x, tid = threadIdx.x;
    __shared__ float qs[DD], kn[DD], vns[DD], es[CHUNK];
    __shared__ float red[4];

    qs[tid]  = g_qkv[0][b][tid];
    kn[tid]  = g_qkv[1][b][tid];
    vns[tid] = g_qkv[2][b][tid];
    __syncthreads();

    int npos = np[b];
    int t0   = c * CHUNK;
    int t    = t0 + tid;

    float e = 0.0f;
    if (t < max_k) {
        float s = 0.0f;
        if (t == npos) {
            #pragma unroll
            for (int d = 0; d < DD; d++) s += qs[d] * kn[d];
        } else {
            const float* krow = kv + ((size_t)b * MAXT + t) * DD;
            #pragma unroll
            for (int d = 0; d < DD; d += 4) {
                float4 kk = *(const float4*)(krow + d);
                s += qs[d]*kk.x + qs[d+1]*kk.y + qs[d+2]*kk.z + qs[d+3]*kk.w;
            }
        }
        e = expf(s * 0.08838834764831845f);   // 1/sqrt(128)
    }
    es[tid]   = e;
    g_e[b][t] = e;

    // chunk denominator: block reduce
    float de = e;
    #pragma unroll
    for (int o = 16; o; o >>= 1) de += __shfl_xor_sync(0xffffffffu, de, o);
    if ((tid & 31) == 0) red[tid >> 5] = de;
    __syncthreads();
    if (tid == 0) g_cden[b][c] = red[0] + red[1] + red[2] + red[3];

    // chunk numerator: thread = dim d, sum over tokens in chunk
    const float* vbase = kv + (size_t)BB * MAXT * DD + ((size_t)b * MAXT + t0) * DD;
    float vnd = vns[tid];
    int   nt  = min(CHUNK, max_k - t0);
    float acc = 0.0f;
    int j = 0;
    for (; j + 8 <= nt; j += 8) {
        float vv[8];
        #pragma unroll
        for (int u = 0; u < 8; u++) vv[u] = vbase[(size_t)(j + u) * DD + tid];
        #pragma unroll
        for (int u = 0; u < 8; u++) {
            float xv = (t0 + j + u == npos) ? vnd : vv[u];
            acc += es[j + u] * xv;
        }
    }
    for (; j < nt; j++) {
        float xv = (t0 + j == npos) ? vnd : vbase[(size_t)j * DD + tid];
        acc += es[j] * xv;
    }
    g_cnum[b][c][tid] = acc;
}

// ---------------------------- K3: prefix scan within chunk + output write
// grid(nchunks, B), 128 threads (thread = dim d).
__global__ __launch_bounds__(128) void scan_kernel(
    const float* __restrict__ kv, const int* __restrict__ np,
    float* __restrict__ out, int max_k) {
    int b = blockIdx.y, c = blockIdx.x, tid = threadIdx.x;
    __shared__ float es[CHUNK], rden[CHUNK], vns[DD];
    __shared__ float warp_sums[4];

    vns[tid] = g_qkv[2][b][tid];
    int t0   = c * CHUNK;
    float e  = g_e[b][t0 + tid];
    es[tid]  = e;

    // inclusive scan of es across the 128 threads (warp scans + combine)
    float v = e;
    int lane = tid & 31, w = tid >> 5;
    #pragma unroll
    for (int o = 1; o < 32; o <<= 1) {
        float n = __shfl_up_sync(0xffffffffu, v, o);
        if (lane >= o) v += n;
    }
    if (lane == 31) warp_sums[w] = v;
    __syncthreads();
    float wbase = 0.0f;
    for (int i = 0; i < w; i++) wbase += warp_sums[i];
    float dpref = v + wbase;   // inclusive intra-chunk denominator prefix

    // denominator base and numerator base from previous chunks
    float den_base = 0.0f;
    for (int i = 0; i < c; i++) den_base += g_cden[b][i];
    float acc = 0.0f;
    for (int i = 0; i < c; i++) acc += g_cnum[b][i][tid];

    int nt = min(CHUNK, max_k - t0);
    if (tid < nt) rden[tid] = 1.0f / (den_base + dpref);
    __syncthreads();

    int npos = np[b];
    const float* vbase = kv + (size_t)BB * MAXT * DD + ((size_t)b * MAXT + t0) * DD;
    float* obase = out + ((size_t)b * max_k + t0) * DD;
    float vnd = vns[tid];

    int j = 0;
    for (; j + 8 <= nt; j += 8) {
        float vv[8];
        #pragma unroll
        for (int u = 0; u < 8; u++) vv[u] = vbase[(size_t)(j + u) * DD + tid];
        #pragma unroll
        for (int u = 0; u < 8; u++) {
            float xv = (t0 + j + u == npos) ? vnd : vv[u];
            acc += es[j + u] * xv;
            obase[(size_t)(j + u) * DD + tid] = acc * rden[j + u];
        }
    }
    for (; j < nt; j++) {
        float xv = (t0 + j == npos) ? vnd : vbase[(size_t)j * DD + tid];
        acc += es[j] * xv;
        obase[(size_t)j * DD + tid] = acc * rden[j];
    }
}

// ----------------------------------------------------------------- launch
extern "C" void kernel_launch(void* const* d_in, const int* in_sizes, int n_in,
                              void* d_out, int out_size) {
    const float* x   = (const float*)d_in[0];
    const float* Wq  = (const float*)d_in[1];
    const float* Wk  = (const float*)d_in[2];
    const float* Wv  = (const float*)d_in[3];
    const float* kvc = (const float*)d_in[4];
    const int*   np  = (const int*)d_in[5];
    float* out = (float*)d_out;

    int max_k   = out_size / (BB * DD);            // = max(next_pos)+1
    int nchunks = (max_k + CHUNK - 1) / CHUNK;

    zero_qkv_kernel<<<48, 256>>>();
    qkv_kernel<<<dim3(12, 32), 256>>>(x, Wq, Wk, Wv);
    score_chunk_kernel<<<dim3(nchunks, BB), 128>>>(kvc, np, max_k);
    scan_kernel<<<dim3(nchunks, BB), 128>>>(kvc, np, out, max_k);
}

// round 2
// speedup vs baseline: 1.0548x; 1.0548x over previous
#include <cuda_runtime.h>

// KVCacheHeadAttention: B=32, E=4096, NH=32 -> D=128, MAX_TOKENS=2048.
// Prefix-softmax: out[b,s,:] = sum_{t<=s} e_t*v[b,t,:] / sum_{t<=s} e_t,
// e_t = exp(q.k_t/sqrt(D)). k/v at t==next_pos[b] substituted with fresh
// projections (inputs untouched).
//
// R2: 512-thread blocks for the two streaming kernels; sub-chunk (32-token)
// partial sums so the scan kernel is single-pass over V with 4x token
// parallelism. Targets the latency-bound signature from R1 ncu
// (occ=14.7%, DRAM=18.5% on scan_kernel).

#define BB 32
#define DD 128
#define EE 4096
#define MAXT 2048
#define CHUNK 128
#define SUB 32
#define MAXSUB 64         // MAXT / SUB

__device__ float g_qkv[3][BB][DD];         // q,k,v projections
__device__ float g_e[BB][MAXT];            // exp(scores)
__device__ float g_cnum[BB][MAXSUB][DD];   // per-sub-chunk numerator partials
__device__ float g_cden[BB][MAXSUB];       // per-sub-chunk denominator partials

// ---------------------------------------------------------------- K0: zero
__global__ void zero_qkv_kernel() {
    int i = blockIdx.x * 256 + threadIdx.x;
    if (i < 3 * BB * DD) ((float*)g_qkv)[i] = 0.0f;
}

// ------------------------------------------------- K1: QKV split-K GEMM
#define ECH 128
__global__ __launch_bounds__(256) void qkv_kernel(
    const float* __restrict__ x, const float* __restrict__ Wq,
    const float* __restrict__ Wk, const float* __restrict__ Wv) {
    __shared__ float xs[32][ECH + 4];
    __shared__ float ws[32][ECH + 4];
    int m  = blockIdx.x >> 2;
    int dt = blockIdx.x & 3;
    const float* W = (m == 0) ? Wq : ((m == 1) ? Wk : Wv);
    int e0  = blockIdx.y * ECH;
    int tid = threadIdx.x;

    for (int i = tid; i < 32 * (ECH / 4); i += 256) {
        int r = i >> 5;
        int j = (i & 31) << 2;
        *(float4*)&xs[r][j] = *(const float4*)(x + (size_t)r * EE + e0 + j);
        *(float4*)&ws[r][j] = *(const float4*)(W + (size_t)(dt * 32 + r) * EE + e0 + j);
    }
    __syncthreads();

    int ti = tid & 15, tj = tid >> 4;
    float a00 = 0.f, a01 = 0.f, a10 = 0.f, a11 = 0.f;
    #pragma unroll
    for (int e = 0; e < ECH; e += 4) {
        float4 xa = *(float4*)&xs[ti][e];
        float4 xb = *(float4*)&xs[ti + 16][e];
        float4 wa = *(float4*)&ws[tj][e];
        float4 wb = *(float4*)&ws[tj + 16][e];
        a00 += xa.x*wa.x + xa.y*wa.y + xa.z*wa.z + xa.w*wa.w;
        a01 += xa.x*wb.x + xa.y*wb.y + xa.z*wb.z + xa.w*wb.w;
        a10 += xb.x*wa.x + xb.y*wa.y + xb.z*wa.z + xb.w*wa.w;
        a11 += xb.x*wb.x + xb.y*wb.y + xb.z*wb.z + xb.w*wb.w;
    }
    atomicAdd(&g_qkv[m][ti][dt * 32 + tj],           a00);
    atomicAdd(&g_qkv[m][ti][dt * 32 + tj + 16],      a01);
    atomicAdd(&g_qkv[m][ti + 16][dt * 32 + tj],      a10);
    atomicAdd(&g_qkv[m][ti + 16][dt * 32 + tj + 16], a11);
}

// ------------- K2: scores -> exp + 32-token sub-chunk num/den partials
// grid(nchunks, B), 512 threads.
// Phase 1: 4 lanes per token (quarter-dot + shfl combine).
// Phase 2: thread = (sub-chunk, dim) partial numerator over 32 tokens.
__global__ __launch_bounds__(512) void score_chunk_kernel(
    const float* __restrict__ kv, const int* __restrict__ np, int max_k) {
    int b = blockIdx.y, c = blockIdx.x, tid = threadIdx.x;
    __shared__ float qs[DD], kn[DD], vns[DD], es[CHUNK];

    if (tid < DD) {
        qs[tid]  = g_qkv[0][b][tid];
        kn[tid]  = g_qkv[1][b][tid];
        vns[tid] = g_qkv[2][b][tid];
    }
    __syncthreads();

    int npos = np[b];
    int t0   = c * CHUNK;

    // --- phase 1: scores. token = tid>>2, quarter = tid&3 (4 lanes/token)
    {
        int tok = tid >> 2, qq = tid & 3;
        int t   = t0 + tok;
        const float* krow = (t == npos) ? kn
                          : kv + ((size_t)b * MAXT + t) * DD;
        float s = 0.0f;
        int d0 = qq * 32;
        #pragma unroll
        for (int d = 0; d < 32; d += 4) {
            float4 kk = *(const float4*)(krow + d0 + d);
            s += qs[d0+d]*kk.x + qs[d0+d+1]*kk.y + qs[d0+d+2]*kk.z + qs[d0+d+3]*kk.w;
        }
        s += __shfl_xor_sync(0xffffffffu, s, 1);
        s += __shfl_xor_sync(0xffffffffu, s, 2);
        float e = (t < max_k) ? expf(s * 0.08838834764831845f) : 0.0f;
        if (qq == 0) {
            es[tok]   = e;
            g_e[b][t] = e;
        }
    }
    __syncthreads();

    // --- sub-chunk denominators: warps 0..3 reduce 32 es each
    if (tid < 128) {
        float de = es[tid];
        #pragma unroll
        for (int o = 16; o; o >>= 1) de += __shfl_xor_sync(0xffffffffu, de, o);
        if ((tid & 31) == 0) g_cden[b][c * 4 + (tid >> 5)] = de;
    }

    // --- phase 2: numerator partials. sc = tid>>7, d = tid&127
    int sc = tid >> 7, d = tid & 127;
    int tb = t0 + sc * SUB;
    const float* vbase = kv + (size_t)BB * MAXT * DD + ((size_t)b * MAXT + tb) * DD;
    float vnd = vns[d];
    int nt = max_k - tb; if (nt > SUB) nt = SUB; if (nt < 0) nt = 0;
    float acc = 0.0f;
    int j = 0;
    for (; j + 8 <= nt; j += 8) {
        float vv[8];
        #pragma unroll
        for (int u = 0; u < 8; u++) vv[u] = vbase[(size_t)(j + u) * DD + d];
        #pragma unroll
        for (int u = 0; u < 8; u++) {
            float xv = (tb + j + u == npos) ? vnd : vv[u];
            acc += es[sc * SUB + j + u] * xv;
        }
    }
    for (; j < nt; j++) {
        float xv = (tb + j == npos) ? vnd : vbase[(size_t)j * DD + d];
        acc += es[sc * SUB + j] * xv;
    }
    g_cnum[b][c * 4 + sc][d] = acc;
}

// --------- K3: prefix scan, 32-token granularity, single V pass
// grid(nchunks, B), 512 threads, thread = (sub-chunk, dim).
__global__ __launch_bounds__(512) void scan_kernel(
    const float* __restrict__ kv, const int* __restrict__ np,
    float* __restrict__ out, int max_k) {
    int b = blockIdx.y, c = blockIdx.x, tid = threadIdx.x;
    __shared__ float es[CHUNK], rden[CHUNK], vns[DD];
    __shared__ float warp_sums[4];

    if (tid < DD) vns[tid] = g_qkv[2][b][tid];
    int t0 = c * CHUNK;
    if (tid < CHUNK) es[tid] = g_e[b][t0 + tid];
    __syncthreads();

    // inclusive denominator prefix across the 128 tokens (threads 0..127)
    float v = 0.0f;
    if (tid < 128) {
        v = es[tid];
        int lane = tid & 31;
        #pragma unroll
        for (int o = 1; o < 32; o <<= 1) {
            float n = __shfl_up_sync(0xffffffffu, v, o);
            if (lane >= o) v += n;
        }
        if (lane == 31) warp_sums[tid >> 5] = v;
    }
    __syncthreads();
    if (tid < 128) {
        int w = tid >> 5;
        float wb = 0.0f;
        for (int i = 0; i < w; i++) wb += warp_sums[i];
        float db = 0.0f;
        for (int i = 0; i < 4 * c; i++) db += g_cden[b][i];
        rden[tid] = 1.0f / (db + wb + v);
    }
    __syncthreads();

    // per-thread: global numerator prefix from earlier sub-chunks, then
    // scan 32 tokens of V and stream the output.
    int sc = tid >> 7, d = tid & 127;
    int tb = t0 + sc * SUB;
    float acc = 0.0f;
    int nsub = c * 4 + sc;
    for (int i = 0; i < nsub; i++) acc += g_cnum[b][i][d];

    int npos = np[b];
    const float* vbase = kv + (size_t)BB * MAXT * DD + ((size_t)b * MAXT + tb) * DD;
    float* obase = out + ((size_t)b * max_k + tb) * DD;
    float vnd = vns[d];
    int nt = max_k - tb; if (nt > SUB) nt = SUB; if (nt < 0) nt = 0;

    int j = 0;
    for (; j + 8 <= nt; j += 8) {
        float vv[8];
        #pragma unroll
        for (int u = 0; u < 8; u++) vv[u] = vbase[(size_t)(j + u) * DD + d];
        #pragma unroll
        for (int u = 0; u < 8; u++) {
            float xv = (tb + j + u == npos) ? vnd : vv[u];
            acc += es[sc * SUB + j + u] * xv;
            obase[(size_t)(j + u) * DD + d] = acc * rden[sc * SUB + j + u];
        }
    }
    for (; j < nt; j++) {
        float xv = (tb + j == npos) ? vnd : vbase[(size_t)j * DD + d];
        acc += es[sc * SUB + j] * xv;
        obase[(size_t)j * DD + d] = acc * rden[sc * SUB + j];
    }
}

// ----------------------------------------------------------------- launch
extern "C" void kernel_launch(void* const* d_in, const int* in_sizes, int n_in,
                              void* d_out, int out_size) {
    const float* x   = (const float*)d_in[0];
    const float* Wq  = (const float*)d_in[1];
    const float* Wk  = (const float*)d_in[2];
    const float* Wv  = (const float*)d_in[3];
    const float* kvc = (const float*)d_in[4];
    const int*   np  = (const int*)d_in[5];
    float* out = (float*)d_out;

    int max_k   = out_size / (BB * DD);
    int nchunks = (max_k + CHUNK - 1) / CHUNK;

    zero_qkv_kernel<<<48, 256>>>();
    qkv_kernel<<<dim3(12, 32), 256>>>(x, Wq, Wk, Wv);
    score_chunk_kernel<<<dim3(nchunks, BB), 512>>>(kvc, np, max_k);
    scan_kernel<<<dim3(nchunks, BB), 512>>>(kvc, np, out, max_k);
}